// round 6
// baseline (speedup 1.0000x reference)
#include <cuda_runtime.h>
#include <cuda_bf16.h>
#include <cstdint>

// VectorQuantizer: bf16 tensor-core SCREEN (single pass) + certified-margin
// EXACT fp32 rescore that replicates R1's arithmetic bit-for-bit.

#define NTOK   131072
#define DDIM   64
#define KCODE  512
#define HWSZ   4096
#define CHW    (64*4096)
#define NELEM  (NTOK*DDIM)

#define NTILES    1024
#define GRID_GEMM 148
#define THR       256
#define MARGIN    3e-3f

// ---- dynamic smem layout (bytes) ----
#define SM_BF    0          // B frags: 8192 x uint2 = 64KB (bf16 high only)
#define SM_XH    65536      // Xh bf16: 128 rows x 144B = 18432
#define SM_XF    83968      // X fp32: 128 rows x 264B = 33792
#define SM_NS    117760     // ns fp32[512] = 2048
#define SM_TOTAL 119808

__device__ int    g_idx[NTOK];
__device__ int    g_counts[KCODE];
__device__ double g_sumsq;

__device__ __forceinline__ uint32_t pkbf(float a, float b) {
    __nv_bfloat162 t = __floats2bfloat162_rn(a, b);
    uint32_t u; memcpy(&u, &t, 4);
    return u;
}
__device__ __forceinline__ unsigned long long pack2(float lo, float hi) {
    unsigned long long r;
    asm("mov.b64 %0, {%1,%2};" : "=l"(r) : "f"(lo), "f"(hi));
    return r;
}
__device__ __forceinline__ void fma2(unsigned long long& d, unsigned long long a, unsigned long long b) {
    asm("fma.rn.f32x2 %0, %1, %2, %0;" : "+l"(d) : "l"(a), "l"(b));
}
__device__ __forceinline__ float2 unpack2(unsigned long long v) {
    float lo, hi;
    asm("mov.b64 {%0,%1}, %2;" : "=f"(lo), "=f"(hi) : "l"(v));
    return make_float2(lo, hi);
}
__device__ __forceinline__ void mma16816(float* c, uint32_t a0, uint32_t a1, uint32_t a2,
                                         uint32_t a3, uint32_t b0, uint32_t b1) {
    asm volatile(
        "mma.sync.aligned.m16n8k16.row.col.f32.bf16.bf16.f32 "
        "{%0,%1,%2,%3}, {%4,%5,%6,%7}, {%8,%9}, {%0,%1,%2,%3};"
        : "+f"(c[0]), "+f"(c[1]), "+f"(c[2]), "+f"(c[3])
        : "r"(a0), "r"(a1), "r"(a2), "r"(a3), "r"(b0), "r"(b1));
}

// keep-5-smallest insert; all indices static after unroll
#define INS(bd, bk, mx, dval, kval) do { \
    if ((dval) < (mx)) { \
        int _ms = 0; float _mv = bd[0]; \
        if (bd[1] > _mv) { _mv = bd[1]; _ms = 1; } \
        if (bd[2] > _mv) { _mv = bd[2]; _ms = 2; } \
        if (bd[3] > _mv) { _mv = bd[3]; _ms = 3; } \
        if (bd[4] > _mv) { _mv = bd[4]; _ms = 4; } \
        _Pragma("unroll") \
        for (int _s = 0; _s < 5; _s++) if (_s == _ms) { bd[_s] = (dval); bk[_s] = (kval); } \
        mx = bd[0]; \
        if (bd[1] > mx) mx = bd[1]; \
        if (bd[2] > mx) mx = bd[2]; \
        if (bd[3] > mx) mx = bd[3]; \
        if (bd[4] > mx) mx = bd[4]; \
    } \
} while (0)

// EXACT distance, replicating R1's instruction sequence:
// 4 f32x2 chains over pair-index p = 4j+c, combine with R1 parens, dist = (a-2m)+n.
__device__ __forceinline__ float exact_dist(const float2* __restrict__ xr,
                                            const float* __restrict__ w,
                                            int k, float aa, float nk) {
    const float2* wr = (const float2*)(w + k * DDIM);
    unsigned long long a0 = 0ull, a1 = 0ull, a2 = 0ull, a3 = 0ull;
#pragma unroll
    for (int j = 0; j < 8; j++) {
        float2 x0 = xr[4*j+0], x1 = xr[4*j+1], x2 = xr[4*j+2], x3 = xr[4*j+3];
        float2 w0 = wr[4*j+0], w1 = wr[4*j+1], w2 = wr[4*j+2], w3 = wr[4*j+3];
        fma2(a0, pack2(x0.x, x0.y), pack2(w0.x, w0.y));
        fma2(a1, pack2(x1.x, x1.y), pack2(w1.x, w1.y));
        fma2(a2, pack2(x2.x, x2.y), pack2(w2.x, w2.y));
        fma2(a3, pack2(x3.x, x3.y), pack2(w3.x, w3.y));
    }
    float2 f0 = unpack2(a0), f1 = unpack2(a1), f2 = unpack2(a2), f3 = unpack2(a3);
    float m = ((f0.x + f0.y) + (f1.x + f1.y)) + ((f2.x + f2.y) + (f3.x + f3.y));
    return (aa - 2.0f * m) + nk;
}

__device__ __forceinline__ void red_min_idx(float& d, int& k) {
#pragma unroll
    for (int off = 1; off <= 2; off <<= 1) {
        float od = __shfl_xor_sync(0xFFFFFFFFu, d, off);
        int   ok = __shfl_xor_sync(0xFFFFFFFFu, k, off);
        if (od < d || (od == d && ok < k)) { d = od; k = ok; }
    }
}

__global__ void vq_init() {
    int t = threadIdx.x;
    if (t < KCODE) g_counts[t] = 0;
    if (t == 0)    g_sumsq = 0.0;
}

extern __shared__ char smem[];

__global__ __launch_bounds__(THR, 1) void vq_gemm(const float* __restrict__ in,
                                                  const float* __restrict__ w) {
    const int tid  = threadIdx.x;
    const int warp = tid >> 5;
    const int lane = tid & 31;

    // ---- one-time staging: ns (R1 association) + single-level B fragments ----
    {
        float* ns = (float*)(smem + SM_NS);
#pragma unroll
        for (int cc = 0; cc < 2; cc++) {
            int c = tid + cc * 256;
            const float4* wr = (const float4*)(w + c * DDIM);
            float nrm = 0.f;
#pragma unroll
            for (int j = 0; j < 16; j++) {
                float4 v = wr[j];
                nrm = fmaf(v.x, v.x, nrm); nrm = fmaf(v.y, v.y, nrm);
                nrm = fmaf(v.z, v.z, nrm); nrm = fmaf(v.w, v.w, nrm);
            }
            ns[c] = nrm;
        }
#pragma unroll
        for (int j = 0; j < 32; j++) {
            int idx = j * 256 + tid;            // nb*128 + kt*32 + ln
            int ln  = idx & 31;
            int kt  = (idx >> 5) & 3;
            int nb  = idx >> 7;
            int n   = nb * 8 + (ln >> 2);
            int k0  = kt * 16 + (ln & 3) * 2;
            float2 fa = *(const float2*)(w + n * DDIM + k0);
            float2 fb = *(const float2*)(w + n * DDIM + k0 + 8);
            uint2 fr;
            fr.x = pkbf(fa.x, fa.y);
            fr.y = pkbf(fb.x, fb.y);
            *(uint2*)(smem + SM_BF + (size_t)idx * 8) = fr;
        }
    }
    __syncthreads();

    const int m = tid & 127;
    const int h = tid >> 7;
    const int r0 = warp * 16 + (lane >> 2);      // rows r0 (Lo), r0+8 (Hi)
    const float* nsf = (const float*)(smem + SM_NS);

    for (int t = blockIdx.x; t < NTILES; t += GRID_GEMM) {
        __syncthreads();   // prev tile fully consumed

        // ---- gather: fp32 -> smem (exact) + bf16 pack for MMA ----
        {
            const int b   = t >> 5;
            const int hw0 = (t & 31) << 7;
            const float* base = in + b * CHW + hw0 + m;
            char* ph = smem + SM_XH + m * 144;
            char* pf = smem + SM_XF + m * 264;
#pragma unroll
            for (int j = 0; j < 32; j += 2) {
                int d = h * 32 + j;
                float x0 = base[d * HWSZ];
                float x1 = base[(d + 1) * HWSZ];
                *(uint32_t*)(ph + d * 2) = pkbf(x0, x1);
                *(float2*)(pf + d * 4)   = make_float2(x0, x1);
            }
        }
        __syncthreads();

        // ---- A fragments (high bf16 only) ----
        uint32_t ah[16];
        {
            const char* pha = smem + SM_XH + r0 * 144 + (lane & 3) * 4;
#pragma unroll
            for (int kt = 0; kt < 4; kt++) {
                ah[kt*4+0] = *(const uint32_t*)(pha + kt * 32);
                ah[kt*4+1] = *(const uint32_t*)(pha + kt * 32 + 8 * 144);
                ah[kt*4+2] = *(const uint32_t*)(pha + kt * 32 + 16);
                ah[kt*4+3] = *(const uint32_t*)(pha + kt * 32 + 8 * 144 + 16);
            }
        }

        // ---- screen: single-pass MMA, keep 5 smallest (d~, k) per row ----
        float bdL[5], bdH[5];
        int   bkL[5], bkH[5];
        float mxL = 3.4e38f, mxH = 3.4e38f;
#pragma unroll
        for (int s = 0; s < 5; s++) { bdL[s] = 3.4e38f; bdH[s] = 3.4e38f; bkL[s] = 0; bkH[s] = 0; }

        for (int nc = 0; nc < 8; nc++) {
#pragma unroll
            for (int nb = 0; nb < 8; nb++) {
                float c[4] = {0.f, 0.f, 0.f, 0.f};
                const char* fb = smem + SM_BF + ((size_t)((nc * 8 + nb) * 128) + lane) * 8;
#pragma unroll
                for (int kt = 0; kt < 4; kt++) {
                    uint2 f = *(const uint2*)(fb + (size_t)kt * 256);
                    mma16816(c, ah[kt*4+0], ah[kt*4+1], ah[kt*4+2], ah[kt*4+3], f.x, f.y);
                }
                int cbase = nc * 64 + nb * 8 + (lane & 3) * 2;
                float2 nn = *(const float2*)(smem + SM_NS + cbase * 4);
                float d0 = fmaf(-2.f, c[0], nn.x);
                float d1 = fmaf(-2.f, c[1], nn.y);
                float d2 = fmaf(-2.f, c[2], nn.x);
                float d3 = fmaf(-2.f, c[3], nn.y);
                INS(bdL, bkL, mxL, d0, cbase);
                INS(bdL, bkL, mxL, d1, cbase + 1);
                INS(bdH, bkH, mxH, d2, cbase);
                INS(bdH, bkH, mxH, d3, cbase + 1);
            }
        }

        // ---- certified-margin exact rescore (R1-replica arithmetic) ----
#pragma unroll
        for (int rr = 0; rr < 2; rr++) {
            float* bd = rr ? bdH : bdL;
            int*   bk = rr ? bkH : bkL;
            int row = r0 + rr * 8;

            float lmin = bd[0];
#pragma unroll
            for (int s = 1; s < 5; s++) lmin = fminf(lmin, bd[s]);
            float gmin = lmin;
#pragma unroll
            for (int off = 1; off <= 2; off <<= 1)
                gmin = fminf(gmin, __shfl_xor_sync(0xFFFFFFFFu, gmin, off));
            float thr = gmin + MARGIN;

            float bde = 3.4e38f;
            int   bke = 0x7FFFFFFF;
            bool any = (bd[0] <= thr) | (bd[1] <= thr) | (bd[2] <= thr)
                     | (bd[3] <= thr) | (bd[4] <= thr);
            if (any) {
                const float2* xr = (const float2*)(smem + SM_XF + row * 264);
                // ||x||^2 exactly as R1: serial fmaf in dim order
                float aa = 0.f;
#pragma unroll
                for (int j = 0; j < 32; j++) {
                    float2 v = xr[j];
                    aa = fmaf(v.x, v.x, aa);
                    aa = fmaf(v.y, v.y, aa);
                }
#pragma unroll
                for (int s = 0; s < 5; s++) {
                    if (bd[s] <= thr) {
                        float de = exact_dist(xr, w, bk[s], aa, nsf[bk[s]]);
                        if (de < bde || (de == bde && bk[s] < bke)) { bde = de; bke = bk[s]; }
                    }
                }
            }
            red_min_idx(bde, bke);
            if ((lane & 3) == 0) {
                g_idx[t * 128 + row] = bke;
                atomicAdd(&g_counts[bke], 1);
            }
        }
    }
}

__global__ __launch_bounds__(512) void vq_scatter(const float* __restrict__ in,
                                                  const float* __restrict__ w,
                                                  float* __restrict__ out) {
    int tid = blockIdx.x * 512 + threadIdx.x;
    int p   = tid << 2;
    int tok = p >> 6;
    int d   = p & 63;
    int kk  = g_idx[tok];

    float4 q  = *reinterpret_cast<const float4*>(w + kk * DDIM + d);
    float4 xv = *reinterpret_cast<const float4*>(in + p);
    reinterpret_cast<float4*>(out)[tid] = q;

    float dx = q.x - xv.x, dy = q.y - xv.y, dz = q.z - xv.z, dw = q.w - xv.w;
    float s = fmaf(dx, dx, fmaf(dy, dy, fmaf(dz, dz, dw * dw)));
#pragma unroll
    for (int off = 16; off > 0; off >>= 1) s += __shfl_xor_sync(0xFFFFFFFFu, s, off);
    __shared__ float red[16];
    int lane = threadIdx.x & 31, wid = threadIdx.x >> 5;
    if (lane == 0) red[wid] = s;
    __syncthreads();
    if (wid == 0) {
        float v = (lane < 16) ? red[lane] : 0.f;
#pragma unroll
        for (int off = 8; off > 0; off >>= 1) v += __shfl_xor_sync(0xFFFFFFFFu, v, off);
        if (lane == 0) atomicAdd(&g_sumsq, (double)v);
    }
}

__global__ void vq_final(float* __restrict__ out) {
    int t = threadIdx.x;
    float c = (float)g_counts[t];
    float p = c / (float)NTOK;
    float term = p * logf(p + 1e-10f);
#pragma unroll
    for (int off = 16; off > 0; off >>= 1) term += __shfl_xor_sync(0xFFFFFFFFu, term, off);
    __shared__ float red[16];
    int lane = t & 31, wid = t >> 5;
    if (lane == 0) red[wid] = term;
    __syncthreads();
    if (t == 0) {
        float H = 0.f;
#pragma unroll
        for (int j = 0; j < 16; j++) H += red[j];
        double mean = g_sumsq / (double)NELEM;
        out[NELEM]     = (float)(1.25 * mean);
        out[NELEM + 1] = expf(-H);
    }
}

extern "C" void kernel_launch(void* const* d_in, const int* in_sizes, int n_in,
                              void* d_out, int out_size) {
    const float* in = (const float*)d_in[0];
    const float* w  = (const float*)d_in[1];
    float* out = (float*)d_out;
    (void)in_sizes; (void)n_in; (void)out_size;

    cudaFuncSetAttribute(vq_gemm, cudaFuncAttributeMaxDynamicSharedMemorySize, SM_TOTAL);

    vq_init<<<1, 512>>>();
    vq_gemm<<<GRID_GEMM, THR, SM_TOTAL>>>(in, w);
    vq_scatter<<<NELEM / 4 / 512, 512>>>(in, w, out);
    vq_final<<<1, 512>>>(out);
}

// round 10
// speedup vs baseline: 1.7276x; 1.7276x over previous
#include <cuda_runtime.h>
#include <cuda_bf16.h>
#include <cstdint>

// VectorQuantizer: branchless bf16 MMA screen (2-pass: value-min, then margin
// collect) + certified exact fp32 rescore replicating R1 arithmetic bit-for-bit.

#define NTOK   131072
#define DDIM   64
#define KCODE  512
#define HWSZ   4096
#define CHW    (64*4096)
#define NELEM  (NTOK*DDIM)

#define NTILES    1024
#define GRID_GEMM 148
#define THR       256
#define MARGIN    3e-3f
#define CAP       24

// ---- dynamic smem layout (bytes) ----
#define SM_BF    0          // B frags: 8192 x uint2 = 64KB
#define SM_XH    65536      // Xh bf16: 128 x 144B = 18432
#define SM_XF    83968      // X fp32: 128 x 264B = 33792
#define SM_NS    117760     // ns fp32[512] = 2048
#define SM_CNT   119808     // int[128]
#define SM_LST   120320     // int[128][CAP] = 12288
#define SM_AA    132608     // float[128]
#define SM_RB    133120     // float[256]
#define SM_RK    134144     // int[256]
#define SM_TOTAL 135168

__device__ int    g_idx[NTOK];
__device__ int    g_counts[KCODE];
__device__ double g_sumsq;

__device__ __forceinline__ uint32_t pkbf(float a, float b) {
    __nv_bfloat162 t = __floats2bfloat162_rn(a, b);
    uint32_t u; memcpy(&u, &t, 4);
    return u;
}
__device__ __forceinline__ unsigned long long pack2(float lo, float hi) {
    unsigned long long r;
    asm("mov.b64 %0, {%1,%2};" : "=l"(r) : "f"(lo), "f"(hi));
    return r;
}
__device__ __forceinline__ void fma2(unsigned long long& d, unsigned long long a, unsigned long long b) {
    asm("fma.rn.f32x2 %0, %1, %2, %0;" : "+l"(d) : "l"(a), "l"(b));
}
__device__ __forceinline__ float2 unpack2(unsigned long long v) {
    float lo, hi;
    asm("mov.b64 {%0,%1}, %2;" : "=f"(lo), "=f"(hi) : "l"(v));
    return make_float2(lo, hi);
}
__device__ __forceinline__ void mma16816(float* c, const uint32_t* a, uint32_t b0, uint32_t b1) {
    asm volatile(
        "mma.sync.aligned.m16n8k16.row.col.f32.bf16.bf16.f32 "
        "{%0,%1,%2,%3}, {%4,%5,%6,%7}, {%8,%9}, {%0,%1,%2,%3};"
        : "+f"(c[0]), "+f"(c[1]), "+f"(c[2]), "+f"(c[3])
        : "r"(a[0]), "r"(a[1]), "r"(a[2]), "r"(a[3]), "r"(b0), "r"(b1));
}

// EXACT distance, replicating R1's instruction sequence (validated in R6).
__device__ __forceinline__ float exact_dist(const float2* __restrict__ xr,
                                            const float* __restrict__ w,
                                            int k, float aa, float nk) {
    const float2* wr = (const float2*)(w + k * DDIM);
    unsigned long long a0 = 0ull, a1 = 0ull, a2 = 0ull, a3 = 0ull;
#pragma unroll
    for (int j = 0; j < 8; j++) {
        float2 x0 = xr[4*j+0], x1 = xr[4*j+1], x2 = xr[4*j+2], x3 = xr[4*j+3];
        float2 w0 = wr[4*j+0], w1 = wr[4*j+1], w2 = wr[4*j+2], w3 = wr[4*j+3];
        fma2(a0, pack2(x0.x, x0.y), pack2(w0.x, w0.y));
        fma2(a1, pack2(x1.x, x1.y), pack2(w1.x, w1.y));
        fma2(a2, pack2(x2.x, x2.y), pack2(w2.x, w2.y));
        fma2(a3, pack2(x3.x, x3.y), pack2(w3.x, w3.y));
    }
    float2 f0 = unpack2(a0), f1 = unpack2(a1), f2 = unpack2(a2), f3 = unpack2(a3);
    float m = ((f0.x + f0.y) + (f1.x + f1.y)) + ((f2.x + f2.y) + (f3.x + f3.y));
    return (aa - 2.0f * m) + nk;
}

__global__ void vq_init() {
    int t = threadIdx.x;
    if (t < KCODE) g_counts[t] = 0;
    if (t == 0)    g_sumsq = 0.0;
}

extern __shared__ char smem[];

__global__ __launch_bounds__(THR, 1) void vq_gemm(const float* __restrict__ in,
                                                  const float* __restrict__ w) {
    const int tid  = threadIdx.x;
    const int warp = tid >> 5;
    const int lane = tid & 31;

    // ---- one-time staging: ns + bf16 B fragments ----
    {
        float* ns = (float*)(smem + SM_NS);
#pragma unroll
        for (int cc = 0; cc < 2; cc++) {
            int c = tid + cc * 256;
            const float4* wr = (const float4*)(w + c * DDIM);
            float nrm = 0.f;
#pragma unroll
            for (int j = 0; j < 16; j++) {
                float4 v = wr[j];
                nrm = fmaf(v.x, v.x, nrm); nrm = fmaf(v.y, v.y, nrm);
                nrm = fmaf(v.z, v.z, nrm); nrm = fmaf(v.w, v.w, nrm);
            }
            ns[c] = nrm;
        }
#pragma unroll
        for (int j = 0; j < 32; j++) {
            int idx = j * 256 + tid;            // nb*128 + kt*32 + ln
            int ln  = idx & 31;
            int kt  = (idx >> 5) & 3;
            int nb  = idx >> 7;
            int n   = nb * 8 + (ln >> 2);
            int k0  = kt * 16 + (ln & 3) * 2;
            float2 fa = *(const float2*)(w + n * DDIM + k0);
            float2 fb = *(const float2*)(w + n * DDIM + k0 + 8);
            uint2 fr;
            fr.x = pkbf(fa.x, fa.y);
            fr.y = pkbf(fb.x, fb.y);
            *(uint2*)(smem + SM_BF + (size_t)idx * 8) = fr;
        }
    }
    __syncthreads();

    const int m  = tid & 127;
    const int h  = tid >> 7;
    const int r0 = warp * 16 + (lane >> 2);      // rows r0 (Lo), r0+8 (Hi)
    const float* nsf = (const float*)(smem + SM_NS);
    int*   cnt = (int*)(smem + SM_CNT);
    int*   lst = (int*)(smem + SM_LST);
    float* aar = (float*)(smem + SM_AA);
    float* rb  = (float*)(smem + SM_RB);
    int*   rk  = (int*)(smem + SM_RK);

    for (int t = blockIdx.x; t < NTILES; t += GRID_GEMM) {
        __syncthreads();   // prev tile fully consumed

        // ---- gather: fp32 -> smem (exact) + bf16 pack for MMA ----
        {
            const int b   = t >> 5;
            const int hw0 = (t & 31) << 7;
            const float* base = in + b * CHW + hw0 + m;
            char* ph = smem + SM_XH + m * 144;
            char* pf = smem + SM_XF + m * 264;
#pragma unroll
            for (int j = 0; j < 32; j += 2) {
                int d = h * 32 + j;
                float x0 = base[d * HWSZ];
                float x1 = base[(d + 1) * HWSZ];
                *(uint32_t*)(ph + d * 2) = pkbf(x0, x1);
                *(float2*)(pf + d * 4)   = make_float2(x0, x1);
            }
            if (h == 0) cnt[m] = 0;
        }
        __syncthreads();

        // ---- A fragments ----
        uint32_t ah[16];
        {
            const char* pha = smem + SM_XH + r0 * 144 + (lane & 3) * 4;
#pragma unroll
            for (int kt = 0; kt < 4; kt++) {
                ah[kt*4+0] = *(const uint32_t*)(pha + kt * 32);
                ah[kt*4+1] = *(const uint32_t*)(pha + kt * 32 + 8 * 144);
                ah[kt*4+2] = *(const uint32_t*)(pha + kt * 32 + 16);
                ah[kt*4+3] = *(const uint32_t*)(pha + kt * 32 + 8 * 144 + 16);
            }
        }

        // ---- pass 1: branchless value-min screen ----
        float dLmin = 3.4e38f, dHmin = 3.4e38f;
        for (int nc = 0; nc < 8; nc++) {
#pragma unroll
            for (int nbp = 0; nbp < 4; nbp++) {
                float c0[4] = {0.f,0.f,0.f,0.f}, c1[4] = {0.f,0.f,0.f,0.f};
                const char* f0p = smem + SM_BF + ((size_t)((nc * 8 + 2*nbp) * 128) + lane) * 8;
#pragma unroll
                for (int kt = 0; kt < 4; kt++) {
                    uint2 f0 = *(const uint2*)(f0p + kt * 256);
                    uint2 f1 = *(const uint2*)(f0p + 1024 + kt * 256);
                    mma16816(c0, ah + kt*4, f0.x, f0.y);
                    mma16816(c1, ah + kt*4, f1.x, f1.y);
                }
                int cb0 = nc * 64 + nbp * 16 + (lane & 3) * 2;
                float2 n0 = *(const float2*)(smem + SM_NS + cb0 * 4);
                float2 n1 = *(const float2*)(smem + SM_NS + (cb0 + 8) * 4);
                dLmin = fminf(dLmin, fmaf(-2.f, c0[0], n0.x));
                dLmin = fminf(dLmin, fmaf(-2.f, c0[1], n0.y));
                dHmin = fminf(dHmin, fmaf(-2.f, c0[2], n0.x));
                dHmin = fminf(dHmin, fmaf(-2.f, c0[3], n0.y));
                dLmin = fminf(dLmin, fmaf(-2.f, c1[0], n1.x));
                dLmin = fminf(dLmin, fmaf(-2.f, c1[1], n1.y));
                dHmin = fminf(dHmin, fmaf(-2.f, c1[2], n1.x));
                dHmin = fminf(dHmin, fmaf(-2.f, c1[3], n1.y));
            }
        }
#pragma unroll
        for (int off = 1; off <= 2; off <<= 1) {
            dLmin = fminf(dLmin, __shfl_xor_sync(0xFFFFFFFFu, dLmin, off));
            dHmin = fminf(dHmin, __shfl_xor_sync(0xFFFFFFFFu, dHmin, off));
        }
        const float thrL = dLmin + MARGIN;
        const float thrH = dHmin + MARGIN;

        // ---- pass 2: recompute (deterministic), collect in-margin candidates ----
        for (int nc = 0; nc < 8; nc++) {
#pragma unroll
            for (int nbp = 0; nbp < 4; nbp++) {
                float c0[4] = {0.f,0.f,0.f,0.f}, c1[4] = {0.f,0.f,0.f,0.f};
                const char* f0p = smem + SM_BF + ((size_t)((nc * 8 + 2*nbp) * 128) + lane) * 8;
#pragma unroll
                for (int kt = 0; kt < 4; kt++) {
                    uint2 f0 = *(const uint2*)(f0p + kt * 256);
                    uint2 f1 = *(const uint2*)(f0p + 1024 + kt * 256);
                    mma16816(c0, ah + kt*4, f0.x, f0.y);
                    mma16816(c1, ah + kt*4, f1.x, f1.y);
                }
                int cb0 = nc * 64 + nbp * 16 + (lane & 3) * 2;
                float2 n0 = *(const float2*)(smem + SM_NS + cb0 * 4);
                float2 n1 = *(const float2*)(smem + SM_NS + (cb0 + 8) * 4);
                float dL0 = fmaf(-2.f, c0[0], n0.x), dL1 = fmaf(-2.f, c0[1], n0.y);
                float dH0 = fmaf(-2.f, c0[2], n0.x), dH1 = fmaf(-2.f, c0[3], n0.y);
                float dL2 = fmaf(-2.f, c1[0], n1.x), dL3 = fmaf(-2.f, c1[1], n1.y);
                float dH2 = fmaf(-2.f, c1[2], n1.x), dH3 = fmaf(-2.f, c1[3], n1.y);
                bool any = (dL0 <= thrL) | (dL1 <= thrL) | (dL2 <= thrL) | (dL3 <= thrL)
                         | (dH0 <= thrH) | (dH1 <= thrH) | (dH2 <= thrH) | (dH3 <= thrH);
                if (__any_sync(0xFFFFFFFFu, any)) {
                    if (dL0 <= thrL) { int s = atomicAdd(&cnt[r0], 1);     if (s < CAP) lst[r0*CAP+s]     = cb0; }
                    if (dL1 <= thrL) { int s = atomicAdd(&cnt[r0], 1);     if (s < CAP) lst[r0*CAP+s]     = cb0+1; }
                    if (dL2 <= thrL) { int s = atomicAdd(&cnt[r0], 1);     if (s < CAP) lst[r0*CAP+s]     = cb0+8; }
                    if (dL3 <= thrL) { int s = atomicAdd(&cnt[r0], 1);     if (s < CAP) lst[r0*CAP+s]     = cb0+9; }
                    if (dH0 <= thrH) { int s = atomicAdd(&cnt[r0+8], 1);   if (s < CAP) lst[(r0+8)*CAP+s] = cb0; }
                    if (dH1 <= thrH) { int s = atomicAdd(&cnt[r0+8], 1);   if (s < CAP) lst[(r0+8)*CAP+s] = cb0+1; }
                    if (dH2 <= thrH) { int s = atomicAdd(&cnt[r0+8], 1);   if (s < CAP) lst[(r0+8)*CAP+s] = cb0+8; }
                    if (dH3 <= thrH) { int s = atomicAdd(&cnt[r0+8], 1);   if (s < CAP) lst[(r0+8)*CAP+s] = cb0+9; }
                }
            }
        }
        __syncthreads();

        // ---- exact ||x||^2 (R1-order serial fmaf), one row per thread<128 ----
        if (tid < 128) {
            const float2* xr = (const float2*)(smem + SM_XF + tid * 264);
            float aa = 0.f;
#pragma unroll
            for (int j = 0; j < 32; j++) {
                float2 v = xr[j];
                aa = fmaf(v.x, v.x, aa);
                aa = fmaf(v.y, v.y, aa);
            }
            aar[tid] = aa;
        }
        __syncthreads();

        // ---- exact rescore: 2 threads per row over its candidate list ----
        {
            int row = tid >> 1, sub = tid & 1;
            int c = min(cnt[row], CAP);
            float bd = 3.4e38f;
            int   bk = 0x7FFFFFFF;
            if (c > 1) {
                const float2* xr = (const float2*)(smem + SM_XF + row * 264);
                float aa = aar[row];
                for (int s = sub; s < c; s += 2) {
                    int k = lst[row*CAP + s];
                    float de = exact_dist(xr, w, k, aa, nsf[k]);
                    if (de < bd || (de == bd && k < bk)) { bd = de; bk = k; }
                }
            }
            rb[tid] = bd;
            rk[tid] = bk;
        }
        __syncthreads();

        if (tid < 128) {
            int c = min(cnt[tid], CAP);
            int kk;
            if (c == 1) kk = lst[tid*CAP];     // certified by margin
            else {
                float f0 = rb[2*tid], f1 = rb[2*tid+1];
                int   k0 = rk[2*tid], k1 = rk[2*tid+1];
                kk = (f1 < f0 || (f1 == f0 && k1 < k0)) ? k1 : k0;
            }
            g_idx[t * 128 + tid] = kk;
            atomicAdd(&g_counts[kk], 1);
        }
    }
}

__global__ __launch_bounds__(512) void vq_scatter(const float* __restrict__ in,
                                                  const float* __restrict__ w,
                                                  float* __restrict__ out) {
    int tid = blockIdx.x * 512 + threadIdx.x;
    int p   = tid << 2;
    int tok = p >> 6;
    int d   = p & 63;
    int kk  = g_idx[tok];

    float4 q  = *reinterpret_cast<const float4*>(w + kk * DDIM + d);
    float4 xv = *reinterpret_cast<const float4*>(in + p);
    reinterpret_cast<float4*>(out)[tid] = q;

    float dx = q.x - xv.x, dy = q.y - xv.y, dz = q.z - xv.z, dw = q.w - xv.w;
    float s = fmaf(dx, dx, fmaf(dy, dy, fmaf(dz, dz, dw * dw)));
#pragma unroll
    for (int off = 16; off > 0; off >>= 1) s += __shfl_xor_sync(0xFFFFFFFFu, s, off);
    __shared__ float red[16];
    int lane = threadIdx.x & 31, wid = threadIdx.x >> 5;
    if (lane == 0) red[wid] = s;
    __syncthreads();
    if (wid == 0) {
        float v = (lane < 16) ? red[lane] : 0.f;
#pragma unroll
        for (int off = 8; off > 0; off >>= 1) v += __shfl_xor_sync(0xFFFFFFFFu, v, off);
        if (lane == 0) atomicAdd(&g_sumsq, (double)v);
    }
}

__global__ void vq_final(float* __restrict__ out) {
    int t = threadIdx.x;
    float c = (float)g_counts[t];
    float p = c / (float)NTOK;
    float term = p * logf(p + 1e-10f);
#pragma unroll
    for (int off = 16; off > 0; off >>= 1) term += __shfl_xor_sync(0xFFFFFFFFu, term, off);
    __shared__ float red[16];
    int lane = t & 31, wid = t >> 5;
    if (lane == 0) red[wid] = term;
    __syncthreads();
    if (t == 0) {
        float H = 0.f;
#pragma unroll
        for (int j = 0; j < 16; j++) H += red[j];
        double mean = g_sumsq / (double)NELEM;
        out[NELEM]     = (float)(1.25 * mean);
        out[NELEM + 1] = expf(-H);
    }
}

extern "C" void kernel_launch(void* const* d_in, const int* in_sizes, int n_in,
                              void* d_out, int out_size) {
    const float* in = (const float*)d_in[0];
    const float* w  = (const float*)d_in[1];
    float* out = (float*)d_out;
    (void)in_sizes; (void)n_in; (void)out_size;

    cudaFuncSetAttribute(vq_gemm, cudaFuncAttributeMaxDynamicSharedMemorySize, SM_TOTAL);

    vq_init<<<1, 512>>>();
    vq_gemm<<<GRID_GEMM, THR, SM_TOTAL>>>(in, w);
    vq_scatter<<<NELEM / 4 / 512, 512>>>(in, w, out);
    vq_final<<<1, 512>>>(out);
}